// round 9
// baseline (speedup 1.0000x reference)
#include <cuda_runtime.h>
#include <cstdint>

// GCNStage4_ReduceSum: out[t] += msg[e] for t = edge_index[1][e]
// msg: [NUM_EDGES, 32] f32; edge_index: [2, NUM_EDGES] int32 (harness); out: [num_nodes, 32] f32
//
// R9: TMA bulk reduction experiment. 5 atomic-shape variants all pinned at
// ~46.5us (L2 RMW wall, 12.8M x 16B fp-add transactions). Replace with ONE
// 128B cp.reduce.async.bulk per edge row (1.6M ops, 8x fewer RMW transactions):
//   LDG msg row -> STS (double-buffered stage) -> fence.proxy.async ->
//   lanes 0-3 issue cp.reduce.async.bulk.add.f32, pipelined via bulk_group.

#define FEAT 32
#define WARPS 8
#define EPI 4      // edges per warp per iteration
#define ITERS 8    // edges per warp = 32

__global__ void __launch_bounds__(256) scatter_bulk_kernel(
        const float4* __restrict__ msg4,
        const int* __restrict__ tgt,
        float* __restrict__ out,
        int num_edges)
{
    // per-warp double-buffered staging: 2 stages x 4 edges x 128B = 1KB/warp
    __shared__ __align__(128) float4 buf[WARPS][2][EPI][8];

    int wid  = threadIdx.x >> 5;
    int lane = threadIdx.x & 31;
    int slot = lane >> 3;          // edge within warp group (0..3)
    int sub  = lane & 7;           // float4 within row
    int warp_base = (blockIdx.x * WARPS + wid) * (EPI * ITERS);

    uint32_t smem_base;
    {
        const void* p = &buf[wid][0][0][0];
        asm("{ .reg .u64 t; cvta.to.shared.u64 t, %1; cvt.u32.u64 %0, t; }"
            : "=r"(smem_base) : "l"(p));
    }

    #pragma unroll
    for (int iter = 0; iter < ITERS; iter++) {
        int stage = iter & 1;

        // stage reuse safety: at most 1 bulk group still un-read
        if (iter >= 2 && lane < EPI)
            asm volatile("cp.async.bulk.wait_group.read 1;" ::: "memory");
        __syncwarp();

        int e = warp_base + iter * EPI + slot;
        int t = -1;
        if (e < num_edges) {
            t = tgt[e];
            buf[wid][stage][slot][sub] = __ldcs(&msg4[(size_t)e * 8 + sub]);
        }
        __syncwarp();

        // route each edge's target to its issuing lane (lane k <- slot k's lane k*8)
        int t_e = __shfl_sync(0xffffffffu, t, (lane & 3) * 8);

        if (lane < EPI) {
            asm volatile("fence.proxy.async.shared::cta;" ::: "memory");
            if (t_e >= 0) {
                uint32_t src = smem_base + (uint32_t)stage * (EPI * 128) + (uint32_t)lane * 128;
                float* dst = out + (size_t)t_e * FEAT;   // 128B-aligned row
                asm volatile(
                    "cp.reduce.async.bulk.global.shared::cta.bulk_group.add.f32 "
                    "[%0], [%1], 128;"
                    :: "l"(dst), "r"(src) : "memory");
            }
            asm volatile("cp.async.bulk.commit_group;" ::: "memory");
        }
    }

    // drain all bulk reductions before exit
    if (lane < EPI)
        asm volatile("cp.async.bulk.wait_group 0;" ::: "memory");
}

extern "C" void kernel_launch(void* const* d_in, const int* in_sizes, int n_in,
                              void* d_out, int out_size) {
    const float4* msg4 = (const float4*)d_in[0];
    const int*    ei   = (const int*)d_in[1];   // int32 indices
    float*        out  = (float*)d_out;

    int num_edges = in_sizes[0] / FEAT;          // 1,600,000
    const int* tgt = ei + num_edges;             // row 1 of edge_index

    // 1) zero the output (poisoned to 0xAA by harness); memset is capturable
    cudaMemsetAsync(d_out, 0, (size_t)out_size * sizeof(float));

    // 2) bulk-reduction scatter: 256 edges per block
    int edges_per_block = WARPS * EPI * ITERS;   // 256
    int blocks = (num_edges + edges_per_block - 1) / edges_per_block;  // 6250 exact
    scatter_bulk_kernel<<<blocks, 256>>>(msg4, tgt, out, num_edges);
}

// round 10
// speedup vs baseline: 1.0704x; 1.0704x over previous
#include <cuda_runtime.h>
#include <cstdint>

// GCNStage4_ReduceSum: out[t] += msg[e] for t = edge_index[1][e]
// msg: [NUM_EDGES, 32] f32; edge_index: [2, NUM_EDGES] int32 (harness); out: [num_nodes, 32] f32
//
// R10: bulk-reduction scatter, overhead-amortized. R9 showed the 128B
// cp.reduce.async.bulk path is SM-issue-bound (issue 48%, alu 39%), not
// RMW-bound. Restage at 16 edges per warp-stage: one fence/commit/syncwarp
// per 16 edges (was per 4), no shuffles (coalesced tgt load), double-buffered
// 2KB stages with wait_group.read 1.

#define FEAT   32
#define WARPS  8
#define E      16    // edges per warp-stage
#define ITERS  4     // 64 edges per warp

__global__ void __launch_bounds__(256) scatter_bulk_kernel(
        const float4* __restrict__ msg4,
        const int* __restrict__ tgt,
        float* __restrict__ out,
        int num_edges)
{
    // per-warp double-buffered staging: 2 stages x 16 edges x 128B = 4KB/warp
    __shared__ __align__(128) float4 buf[WARPS][2][E][8];

    int wid  = threadIdx.x >> 5;
    int lane = threadIdx.x & 31;
    int grp  = lane >> 3;          // edge-within-pass (0..3)
    int sub  = lane & 7;           // float4 within row
    int warp_base = (blockIdx.x * WARPS + wid) * (E * ITERS);

    uint32_t smem_warp;
    {
        const void* p = &buf[wid][0][0][0];
        asm("{ .reg .u64 t; cvta.to.shared.u64 t, %1; cvt.u32.u64 %0, t; }"
            : "=r"(smem_warp) : "l"(p));
    }

    #pragma unroll
    for (int iter = 0; iter < ITERS; iter++) {
        int stage = iter & 1;

        // before reusing this stage, its previous bulk group must be read out
        if (iter >= 2 && lane < E)
            asm volatile("cp.async.bulk.wait_group.read 1;" ::: "memory");
        __syncwarp();

        int base_e = warp_base + iter * E;

        // load 16 edge rows: 4 coalesced passes of 4 edges (512B contiguous each)
        #pragma unroll
        for (int p = 0; p < 4; p++) {
            int s = p * 4 + grp;                 // edge slot 0..15
            int e = base_e + s;
            if (e < num_edges)
                buf[wid][stage][s][sub] = __ldcs(&msg4[(size_t)e * 8 + sub]);
        }

        // coalesced target load: lane k -> tgt[base_e + k]
        int t = -1;
        if (lane < E) {
            int e = base_e + lane;
            if (e < num_edges) t = tgt[e];
        }
        __syncwarp();

        if (lane < E) {
            asm volatile("fence.proxy.async.shared::cta;" ::: "memory");
            if (t >= 0) {
                uint32_t src = smem_warp + (uint32_t)stage * (E * 128) + (uint32_t)lane * 128;
                float* dst = out + (size_t)t * FEAT;   // 128B-aligned row
                asm volatile(
                    "cp.reduce.async.bulk.global.shared::cta.bulk_group.add.f32 "
                    "[%0], [%1], 128;"
                    :: "l"(dst), "r"(src) : "memory");
            }
            asm volatile("cp.async.bulk.commit_group;" ::: "memory");
        }
    }

    // drain all bulk reductions before exit
    if (lane < E)
        asm volatile("cp.async.bulk.wait_group 0;" ::: "memory");
}

extern "C" void kernel_launch(void* const* d_in, const int* in_sizes, int n_in,
                              void* d_out, int out_size) {
    const float4* msg4 = (const float4*)d_in[0];
    const int*    ei   = (const int*)d_in[1];   // int32 indices
    float*        out  = (float*)d_out;

    int num_edges = in_sizes[0] / FEAT;          // 1,600,000
    const int* tgt = ei + num_edges;             // row 1 of edge_index

    // 1) zero the output (poisoned to 0xAA by harness); memset is capturable
    cudaMemsetAsync(d_out, 0, (size_t)out_size * sizeof(float));

    // 2) bulk-reduction scatter: 512 edges per block
    int edges_per_block = WARPS * E * ITERS;     // 512
    int blocks = (num_edges + edges_per_block - 1) / edges_per_block;  // 3125 exact
    scatter_bulk_kernel<<<blocks, 256>>>(msg4, tgt, out, num_edges);
}